// round 1
// baseline (speedup 1.0000x reference)
#include <cuda_runtime.h>
#include <math.h>

#define NB 256      // batch
#define CC 256      // channels
#define TT 64       // time
#define VV 25       // vertices (input SPD dim)
#define DD 10       // final SPD dim after W1*W2*W3
#define OUTD 64
#define FEATD 100

// scratch (allocation-free rule: __device__ globals)
__device__ float g_xm[NB * CC * VV];     // temporal means, 6.55 MB
__device__ float g_Wc[VV * DD];          // W1@W2@W3  (25x10)

// ---------------------------------------------------------------------------
// Kernel C: Wc = W1(25x20) @ W2(20x15) @ W3(15x10)
// ---------------------------------------------------------------------------
__global__ void wc_kernel(const float* __restrict__ W1,
                          const float* __restrict__ W2,
                          const float* __restrict__ W3) {
    __shared__ float t15[25 * 15];
    int tid = threadIdx.x;
    for (int e = tid; e < 25 * 15; e += blockDim.x) {
        int i = e / 15, j = e % 15;
        float s = 0.f;
        #pragma unroll
        for (int k = 0; k < 20; k++) s += W1[i * 20 + k] * W2[k * 15 + j];
        t15[e] = s;
    }
    __syncthreads();
    for (int e = tid; e < VV * DD; e += blockDim.x) {
        int i = e / DD, j = e % DD;
        float s = 0.f;
        #pragma unroll
        for (int k = 0; k < 15; k++) s += t15[i * 15 + k] * W3[k * DD + j];
        g_Wc[e] = s;
    }
}

// ---------------------------------------------------------------------------
// Kernel A: xm[n,c,v] = mean_t x[n,c,t,v].  One warp per (n,c); 25 active
// lanes; the 6400-byte row is contiguous so every fetched sector is consumed.
// ---------------------------------------------------------------------------
__global__ void meanT_kernel(const float* __restrict__ x) {
    int gw   = (blockIdx.x * blockDim.x + threadIdx.x) >> 5;  // (n,c) index
    int lane = threadIdx.x & 31;
    if (gw >= NB * CC || lane >= VV) return;
    const float* p = x + (size_t)gw * (TT * VV) + lane;
    float a0 = 0.f, a1 = 0.f, a2 = 0.f, a3 = 0.f;
    #pragma unroll
    for (int t = 0; t < TT; t += 4) {
        a0 += p[(t + 0) * VV];
        a1 += p[(t + 1) * VV];
        a2 += p[(t + 2) * VV];
        a3 += p[(t + 3) * VV];
    }
    g_xm[gw * VV + lane] = (a0 + a1 + a2 + a3) * (1.0f / TT);
}

// ---------------------------------------------------------------------------
// Kernel B: per batch sample n (one block, 128 threads):
//   y = xm @ Wc (256x10); center over c; A = y'y'/(C-1) + 1e-8 I (10x10);
//   Jacobi eigh; L = V log(w) V^T; out = L.flat @ fc_w^T + fc_b
// ---------------------------------------------------------------------------
__global__ void __launch_bounds__(128)
spd_kernel(const float* __restrict__ fcw, const float* __restrict__ fcb,
           float* __restrict__ out) {
    __shared__ float sxm[CC * VV];     // 6400
    __shared__ float sy [CC * DD];     // 2560
    __shared__ float sWc[VV * DD];     // 250
    __shared__ float sm [DD];
    __shared__ float A  [DD * DD];
    __shared__ float Vv [DD * DD];
    __shared__ float rc[5], rs[5];
    __shared__ int   rp[5], rq[5];
    __shared__ float lw [DD];
    __shared__ float L  [DD * DD];

    const int n   = blockIdx.x;
    const int tid = threadIdx.x;

    for (int e = tid; e < VV * DD; e += 128) sWc[e] = g_Wc[e];
    for (int e = tid; e < CC * VV; e += 128) sxm[e] = g_xm[n * CC * VV + e];
    __syncthreads();

    // project each channel row: y[c,:] = xm[c,:] @ Wc
    for (int c = tid; c < CC; c += 128) {
        float xr[VV];
        #pragma unroll
        for (int v = 0; v < VV; v++) xr[v] = sxm[c * VV + v];
        #pragma unroll
        for (int o = 0; o < DD; o++) {
            float s = 0.f;
            #pragma unroll
            for (int v = 0; v < VV; v++) s += xr[v] * sWc[v * DD + o];
            sy[c * DD + o] = s;
        }
    }
    __syncthreads();

    // mean over channels
    if (tid < DD) {
        float s = 0.f;
        for (int c = 0; c < CC; c++) s += sy[c * DD + tid];
        sm[tid] = s * (1.0f / CC);
    }
    __syncthreads();
    for (int e = tid; e < CC * DD; e += 128) sy[e] -= sm[e % DD];
    __syncthreads();

    // Gram -> covariance (55 upper-tri entries)
    if (tid < 55) {
        int e = tid, o = 0;
        while (e >= DD - o) { e -= DD - o; o++; }
        int p2 = o + e;
        float s = 0.f;
        for (int c = 0; c < CC; c++) s += sy[c * DD + o] * sy[c * DD + p2];
        float val = s * (1.0f / (CC - 1)) + (o == p2 ? 1e-8f : 0.f);
        A[o * DD + p2] = val;
        A[p2 * DD + o] = val;
    }
    if (tid < DD * DD) Vv[tid] = ((tid / DD) == (tid % DD)) ? 1.f : 0.f;
    __syncthreads();

    // ---- parallel cyclic Jacobi: 5 disjoint pairs/round, 9 rounds/sweep ----
    for (int sweep = 0; sweep < 6; sweep++) {
        for (int r = 0; r < 9; r++) {
            if (tid < 5) {
                int k  = tid;
                int i1 = (k == 0) ? 0 : ((r + k - 1) % 9) + 1;
                int i2 = ((r + 8 - k) % 9) + 1;
                int p = min(i1, i2), q = max(i1, i2);
                rp[k] = p; rq[k] = q;
                float apq = A[p * DD + q];
                float c = 1.f, s = 0.f;
                if (fabsf(apq) > 1e-18f) {
                    float tau = (A[q * DD + q] - A[p * DD + p]) / (2.f * apq);
                    float t   = copysignf(1.f, tau) /
                                (fabsf(tau) + sqrtf(1.f + tau * tau));
                    c = 1.f / sqrtf(1.f + t * t);
                    s = t * c;
                }
                rc[k] = c; rs[k] = s;
            }
            __syncthreads();
            // row phase: A <- J^T A
            if (tid < 50) {
                int k = tid / DD, j = tid % DD;
                int p = rp[k], q = rq[k];
                float c = rc[k], s = rs[k];
                float a = A[p * DD + j], b = A[q * DD + j];
                A[p * DD + j] = c * a - s * b;
                A[q * DD + j] = s * a + c * b;
            }
            __syncthreads();
            // col phase: A <- A J ;  V <- V J
            if (tid < 50) {
                int k = tid / DD, i = tid % DD;
                int p = rp[k], q = rq[k];
                float c = rc[k], s = rs[k];
                float a = A[i * DD + p], b = A[i * DD + q];
                A[i * DD + p] = c * a - s * b;
                A[i * DD + q] = s * a + c * b;
            } else if (tid < 100) {
                int k = (tid - 50) / DD, i = (tid - 50) % DD;
                int p = rp[k], q = rq[k];
                float c = rc[k], s = rs[k];
                float a = Vv[i * DD + p], b = Vv[i * DD + q];
                Vv[i * DD + p] = c * a - s * b;
                Vv[i * DD + q] = s * a + c * b;
            }
            __syncthreads();
        }
    }

    // logm: L = V diag(log w) V^T
    if (tid < DD) lw[tid] = logf(fmaxf(A[tid * DD + tid], 1e-12f));
    __syncthreads();
    if (tid < FEATD) {
        int i = tid / DD, j = tid % DD;
        float s = 0.f;
        #pragma unroll
        for (int k = 0; k < DD; k++) s += Vv[i * DD + k] * lw[k] * Vv[j * DD + k];
        L[tid] = s;
    }
    __syncthreads();

    // FC: out[n,m] = b[m] + sum_f L[f] * fc_w[m,f]
    if (tid < OUTD) {
        float s = fcb[tid];
        #pragma unroll 4
        for (int f = 0; f < FEATD; f++) s += L[f] * fcw[tid * FEATD + f];
        out[n * OUTD + tid] = s;
    }
}

// ---------------------------------------------------------------------------
extern "C" void kernel_launch(void* const* d_in, const int* in_sizes, int n_in,
                              void* d_out, int out_size) {
    const float *x = nullptr, *W1 = nullptr, *W2 = nullptr, *W3 = nullptr;
    const float *fcw = nullptr, *fcb = nullptr;
    for (int i = 0; i < n_in; i++) {
        switch (in_sizes[i]) {
            case NB * CC * TT * VV: x   = (const float*)d_in[i]; break;
            case 500:               W1  = (const float*)d_in[i]; break;
            case 300:               W2  = (const float*)d_in[i]; break;
            case 150:               W3  = (const float*)d_in[i]; break;
            case 6400:              fcw = (const float*)d_in[i]; break;
            case 64:                fcb = (const float*)d_in[i]; break;
            default: break;
        }
    }

    wc_kernel<<<1, 128>>>(W1, W2, W3);

    // one warp per (n,c): 65536 warps -> 8192 blocks of 256 threads
    meanT_kernel<<<(NB * CC) / 8, 256>>>(x);

    spd_kernel<<<NB, 128>>>(fcw, fcb, (float*)d_out);
}

// round 2
// speedup vs baseline: 1.1315x; 1.1315x over previous
#include <cuda_runtime.h>
#include <math.h>

#define NB 256      // batch
#define CC 256      // channels
#define TT 64       // time
#define VV 25       // vertices (input SPD dim)
#define DD 10       // final SPD dim after W1*W2*W3
#define OUTD 64
#define FEATD 100

// scratch (allocation-free rule: __device__ global)
__device__ float g_y[NB * CC * DD];      // projected per-(n,c) 10-vectors, 2.6 MB

// ---------------------------------------------------------------------------
// Kernel 1 (fused): per (n,c) row, mean over t (25-dim), then project through
// Wc = W1@W2@W3 (computed redundantly per block, ~11K FMA) to a 10-vector.
// One warp per row; lanes 0-24 hold xm, projection via 25 shfl broadcasts.
// This kernel does the single 419 MB streaming pass -> should pin DRAM.
// ---------------------------------------------------------------------------
__global__ void __launch_bounds__(256)
meanproj_kernel(const float* __restrict__ x,
                const float* __restrict__ W1,
                const float* __restrict__ W2,
                const float* __restrict__ W3) {
    __shared__ float t15[VV * 15];
    __shared__ float sWc[VV * DD + 32];   // padded so lanes>=10 can read safely

    const int tid = threadIdx.x;

    // Wc = (W1 @ W2) @ W3 in smem
    for (int e = tid; e < VV * 15; e += 256) {
        int i = e / 15, j = e % 15;
        float s = 0.f;
        #pragma unroll
        for (int k = 0; k < 20; k++) s += W1[i * 20 + k] * W2[k * 15 + j];
        t15[e] = s;
    }
    __syncthreads();
    for (int e = tid; e < VV * DD + 32; e += 256) {
        if (e < VV * DD) {
            int i = e / DD, j = e % DD;
            float s = 0.f;
            #pragma unroll
            for (int k = 0; k < 15; k++) s += t15[i * 15 + k] * W3[k * DD + j];
            sWc[e] = s;
        } else {
            sWc[e] = 0.f;
        }
    }
    __syncthreads();

    const int warp = tid >> 5, lane = tid & 31;
    const int gw = blockIdx.x * 8 + warp;           // (n,c) row index

    float xm = 0.f;
    if (lane < VV) {
        const float* p = x + (size_t)gw * (TT * VV) + lane;
        float a0 = 0.f, a1 = 0.f, a2 = 0.f, a3 = 0.f;
        #pragma unroll
        for (int t = 0; t < TT; t += 4) {
            a0 += p[(t + 0) * VV];
            a1 += p[(t + 1) * VV];
            a2 += p[(t + 2) * VV];
            a3 += p[(t + 3) * VV];
        }
        xm = (a0 + a1 + a2 + a3) * (1.0f / TT);
    }

    // y[o] = sum_v xm[v] * Wc[v][o]  via warp broadcasts
    float y = 0.f;
    #pragma unroll
    for (int v = 0; v < VV; v++) {
        float xv = __shfl_sync(0xffffffffu, xm, v);
        y += xv * sWc[v * DD + lane];               // lanes >=10 read pad
    }
    if (lane < DD) g_y[gw * DD + lane] = y;
}

// ---------------------------------------------------------------------------
// Kernel 2: per sample n (one block, 128 threads):
//   load y (10 KB), center over c, A = y'y'/(C-1) + 1e-8 I (10x10),
//   parallel Jacobi eigh (5 sweeps), L = V log(w) V^T, out = L @ fc_w^T + b
// All 256 blocks resident in one wave -> duration == per-block latency.
// ---------------------------------------------------------------------------
__global__ void __launch_bounds__(128)
spd_kernel(const float* __restrict__ fcw, const float* __restrict__ fcb,
           float* __restrict__ out) {
    __shared__ float sy   [CC * DD];      // 10240 B
    __shared__ float pmean[8 * DD];
    __shared__ float smn  [DD];
    __shared__ float pg   [55 * 2];
    __shared__ float A    [DD * DD];
    __shared__ float Vv   [DD * DD];
    __shared__ float rc[5], rs[5];
    __shared__ int   rp[5], rq[5];
    __shared__ float lw   [DD];
    __shared__ float L    [FEATD];

    const int n   = blockIdx.x;
    const int tid = threadIdx.x;

    // coalesced float4 load of this sample's projected vectors
    {
        const float4* src = (const float4*)(g_y + (size_t)n * CC * DD);
        float4* dst = (float4*)sy;
        #pragma unroll
        for (int e = tid; e < CC * DD / 4; e += 128) dst[e] = src[e];
    }
    __syncthreads();

    // channel mean: 80-way partials, then combine
    if (tid < 80) {
        int o = tid % DD, seg = tid / DD;
        float s = 0.f;
        #pragma unroll 8
        for (int c = seg * 32; c < seg * 32 + 32; c++) s += sy[c * DD + o];
        pmean[seg * DD + o] = s;
    }
    __syncthreads();
    if (tid < DD) {
        float s = 0.f;
        #pragma unroll
        for (int k = 0; k < 8; k++) s += pmean[k * DD + tid];
        smn[tid] = s * (1.0f / CC);
    }
    __syncthreads();
    for (int e = tid; e < CC * DD; e += 128) sy[e] -= smn[e % DD];
    __syncthreads();

    // Gram: 110-way partials (55 upper-tri pairs x 2 channel halves)
    if (tid < 110) {
        int k = tid % 55, h = tid / 55;
        int e = k, o = 0;
        while (e >= DD - o) { e -= DD - o; o++; }
        int q = o + e;
        float s = 0.f;
        #pragma unroll 8
        for (int c = h * 128; c < h * 128 + 128; c++)
            s += sy[c * DD + o] * sy[c * DD + q];
        pg[k * 2 + h] = s;
    }
    __syncthreads();
    if (tid < 55) {
        int e = tid, o = 0;
        while (e >= DD - o) { e -= DD - o; o++; }
        int q = o + e;
        float val = (pg[tid * 2] + pg[tid * 2 + 1]) * (1.0f / (CC - 1))
                  + (o == q ? 1e-8f : 0.f);
        A[o * DD + q] = val;
        A[q * DD + o] = val;
    }
    if (tid < DD * DD) Vv[tid] = ((tid / DD) == (tid % DD)) ? 1.f : 0.f;
    __syncthreads();

    // ---- parallel cyclic Jacobi: 5 disjoint pairs/round, 9 rounds/sweep ----
    for (int sweep = 0; sweep < 5; sweep++) {
        for (int r = 0; r < 9; r++) {
            if (tid < 5) {
                int k  = tid;
                int i1 = (k == 0) ? 0 : ((r + k - 1) % 9) + 1;
                int i2 = ((r + 8 - k) % 9) + 1;
                int p = min(i1, i2), q = max(i1, i2);
                rp[k] = p; rq[k] = q;
                float apq = A[p * DD + q];
                float c = 1.f, s = 0.f;
                if (fabsf(apq) > 1e-18f) {
                    float tau = (A[q * DD + q] - A[p * DD + p]) / (2.f * apq);
                    float t   = copysignf(1.f, tau) /
                                (fabsf(tau) + sqrtf(1.f + tau * tau));
                    c = 1.f / sqrtf(1.f + t * t);
                    s = t * c;
                }
                rc[k] = c; rs[k] = s;
            }
            __syncthreads();
            // row phase: A <- J^T A
            if (tid < 50) {
                int k = tid / DD, j = tid % DD;
                int p = rp[k], q = rq[k];
                float c = rc[k], s = rs[k];
                float a = A[p * DD + j], b = A[q * DD + j];
                A[p * DD + j] = c * a - s * b;
                A[q * DD + j] = s * a + c * b;
            }
            __syncthreads();
            // col phase: A <- A J ;  V <- V J
            if (tid < 50) {
                int k = tid / DD, i = tid % DD;
                int p = rp[k], q = rq[k];
                float c = rc[k], s = rs[k];
                float a = A[i * DD + p], b = A[i * DD + q];
                A[i * DD + p] = c * a - s * b;
                A[i * DD + q] = s * a + c * b;
            } else if (tid < 100) {
                int k = (tid - 50) / DD, i = (tid - 50) % DD;
                int p = rp[k], q = rq[k];
                float c = rc[k], s = rs[k];
                float a = Vv[i * DD + p], b = Vv[i * DD + q];
                Vv[i * DD + p] = c * a - s * b;
                Vv[i * DD + q] = s * a + c * b;
            }
            __syncthreads();
        }
    }

    // logm: L = V diag(log w) V^T
    if (tid < DD) lw[tid] = logf(fmaxf(A[tid * DD + tid], 1e-12f));
    __syncthreads();
    if (tid < FEATD) {
        int i = tid / DD, j = tid % DD;
        float s = 0.f;
        #pragma unroll
        for (int k = 0; k < DD; k++) s += Vv[i * DD + k] * lw[k] * Vv[j * DD + k];
        L[tid] = s;
    }
    __syncthreads();

    // FC: out[n,m] = b[m] + sum_f L[f] * fc_w[m,f]
    if (tid < OUTD) {
        float s = fcb[tid];
        #pragma unroll 4
        for (int f = 0; f < FEATD; f++) s += L[f] * fcw[tid * FEATD + f];
        out[n * OUTD + tid] = s;
    }
}

// ---------------------------------------------------------------------------
extern "C" void kernel_launch(void* const* d_in, const int* in_sizes, int n_in,
                              void* d_out, int out_size) {
    const float *x = nullptr, *W1 = nullptr, *W2 = nullptr, *W3 = nullptr;
    const float *fcw = nullptr, *fcb = nullptr;
    for (int i = 0; i < n_in; i++) {
        switch (in_sizes[i]) {
            case NB * CC * TT * VV: x   = (const float*)d_in[i]; break;
            case 500:               W1  = (const float*)d_in[i]; break;
            case 300:               W2  = (const float*)d_in[i]; break;
            case 150:               W3  = (const float*)d_in[i]; break;
            case 6400:              fcw = (const float*)d_in[i]; break;
            case 64:                fcb = (const float*)d_in[i]; break;
            default: break;
        }
    }

    // one warp per (n,c) row: 65536 rows -> 8192 blocks x 8 warps
    meanproj_kernel<<<(NB * CC) / 8, 256>>>(x, W1, W2, W3);

    spd_kernel<<<NB, 128>>>(fcw, fcb, (float*)d_out);
}